// round 5
// baseline (speedup 1.0000x reference)
#include <cuda_runtime.h>

#define NN 50000
#define NE 640000
#define DD 128
#define NG 64

// ---- scratch: __device__ globals only (16B-aligned for float4 access) ----
__device__ __align__(16) float g_h[NN * DD];     // h = X @ W   (25.6 MB)
__device__ __align__(16) float g_agg[NN * DD];   // per-layer aggregation (25.6 MB)
__device__ float g_dinv[NN];
__device__ int   g_deg[NN];
__device__ int   g_cnt[NG];

// ---- zero deg / cnt / out ----
__global__ void zero_kernel(float* __restrict__ out) {
    int i = blockIdx.x * blockDim.x + threadIdx.x;
    if (i < NN) g_deg[i] = 0;
    if (i < NG) g_cnt[i] = 0;
    if (i < NG * DD) out[i] = 0.0f;
}

// ---- degree histogram over dst (edge_index is int32, layout [2, NE]) ----
__global__ void deg_kernel(const int* __restrict__ ei) {
    int e = blockIdx.x * blockDim.x + threadIdx.x;
    if (e < NE) atomicAdd(&g_deg[ei[NE + e]], 1);
}

__global__ void dinv_kernel() {
    int i = blockIdx.x * blockDim.x + threadIdx.x;
    if (i < NN) g_dinv[i] = rsqrtf((float)g_deg[i] + 1.0f);
}

// ---- GEMM body: out[N,128] = (RELU? relu(in) : in) @ W[128,128] ----
// 256 threads, 64 rows/block. Static smem 48KB: W K-chunk 64x128 (32KB) +
// X tile 64x64 (16KB). Two K-chunks; accumulators in registers.
// Thread computes 8 rows x 4 cols. Ws reads stride-1 across lanes; Xs reads
// warp-broadcast -> conflict-free.
template <bool RELU>
__device__ __forceinline__ void gemm_body(const float* __restrict__ in,
                                          const float* __restrict__ W,
                                          float* __restrict__ out) {
    __shared__ float Ws[64 * DD];   // 32 KB
    __shared__ float Xs[64 * 64];   // 16 KB
    int t = threadIdx.x;
    int row0 = blockIdx.x * 64;
    int c = t & 31;          // column base: c, c+32, c+64, c+96
    int rb = (t >> 5) * 8;   // 8 rows per thread

    float acc[8][4];
#pragma unroll
    for (int r = 0; r < 8; r++)
#pragma unroll
        for (int j = 0; j < 4; j++) acc[r][j] = 0.f;

#pragma unroll
    for (int kc = 0; kc < 2; kc++) {
        // load W rows [kc*64, kc*64+64), all 128 cols: 2048 float4
        const float4* W4 = (const float4*)(W + kc * 64 * DD);
        float4* Ws4 = (float4*)Ws;
#pragma unroll
        for (int i = 0; i < 8; i++) Ws4[t + 256 * i] = W4[t + 256 * i];

        // load X tile: 64 rows x 64 k-vals = 1024 float4 (16 float4/row)
        float4* Xs4 = (float4*)Xs;
#pragma unroll
        for (int i = 0; i < 4; i++) {
            int idx = t + 256 * i;
            int r = idx >> 4, c4 = idx & 15;
            float4 v = make_float4(0.f, 0.f, 0.f, 0.f);
            int row = row0 + r;
            if (row < NN) {
                v = ((const float4*)(in + (size_t)row * DD + kc * 64))[c4];
                if (RELU) {
                    v.x = fmaxf(v.x, 0.f); v.y = fmaxf(v.y, 0.f);
                    v.z = fmaxf(v.z, 0.f); v.w = fmaxf(v.w, 0.f);
                }
            }
            Xs4[idx] = v;
        }
        __syncthreads();

#pragma unroll 4
        for (int k = 0; k < 64; k++) {
            float w0 = Ws[k * DD + c];
            float w1 = Ws[k * DD + c + 32];
            float w2 = Ws[k * DD + c + 64];
            float w3 = Ws[k * DD + c + 96];
#pragma unroll
            for (int r = 0; r < 8; r++) {
                float xv = Xs[(rb + r) * 64 + k];
                acc[r][0] = fmaf(xv, w0, acc[r][0]);
                acc[r][1] = fmaf(xv, w1, acc[r][1]);
                acc[r][2] = fmaf(xv, w2, acc[r][2]);
                acc[r][3] = fmaf(xv, w3, acc[r][3]);
            }
        }
        __syncthreads();
    }

#pragma unroll
    for (int r = 0; r < 8; r++) {
        int row = row0 + rb + r;
        if (row < NN) {
            float* o = out + (size_t)row * DD;
            o[c]      = acc[r][0];
            o[c + 32] = acc[r][1];
            o[c + 64] = acc[r][2];
            o[c + 96] = acc[r][3];
        }
    }
}

// layer 1: in = external x, out = g_h
__global__ void __launch_bounds__(256) gemm1_kernel(const float* __restrict__ x,
                                                    const float* __restrict__ W) {
    gemm_body<false>(x, W, g_h);
}
// layer 2: in = relu(g_agg), out = g_h
__global__ void __launch_bounds__(256) gemm2_kernel(const float* __restrict__ W) {
    gemm_body<true>(g_agg, W, g_h);
}

// ---- agg init: self-loop term + bias:  agg[i] = h[i]*dinv_i^2 + b ----
__global__ void init_agg_kernel(const float* __restrict__ b) {
    int idx = blockIdx.x * blockDim.x + threadIdx.x;  // over NN*32 float4
    if (idx >= NN * 32) return;
    int i = idx >> 5;
    int c4 = (idx & 31) * 4;
    float di = g_dinv[i];
    float s = di * di;
    float4 h = ((const float4*)g_h)[idx];
    float4 o;
    o.x = fmaf(h.x, s, b[c4 + 0]);
    o.y = fmaf(h.y, s, b[c4 + 1]);
    o.z = fmaf(h.z, s, b[c4 + 2]);
    o.w = fmaf(h.w, s, b[c4 + 3]);
    ((float4*)g_agg)[idx] = o;
}

// ---- edge scatter: warp per edge, lane handles 4 channels ----
__global__ void scatter_kernel(const int* __restrict__ ei) {
    int e = (blockIdx.x * blockDim.x + threadIdx.x) >> 5;
    if (e >= NE) return;
    int lane = threadIdx.x & 31;
    int src = ei[e];
    int dst = ei[NE + e];
    float norm = g_dinv[src] * g_dinv[dst];
    float4 h = ((const float4*)(g_h + (size_t)src * DD))[lane];
    float* a = g_agg + (size_t)dst * DD + lane * 4;
    atomicAdd(a + 0, h.x * norm);
    atomicAdd(a + 1, h.y * norm);
    atomicAdd(a + 2, h.z * norm);
    atomicAdd(a + 3, h.w * norm);
}

// ---- segmented mean pool (batch sorted): 128 thr = channels, 256 nodes/block ----
#define POOL_CH 256
__global__ void pool_kernel(const int* __restrict__ batch, float* __restrict__ out) {
    __shared__ int sb[POOL_CH];
    int t = threadIdx.x;  // 128
    int base = blockIdx.x * POOL_CH;
    int nn = min(POOL_CH, NN - base);
    for (int i = t; i < nn; i += 128) sb[i] = batch[base + i];
    __syncthreads();
    for (int i = t; i < nn; i += 128) atomicAdd(&g_cnt[sb[i]], 1);

    float s = 0.f;
    int cur = sb[0];
    for (int i = 0; i < nn; i++) {
        int g = sb[i];
        if (g != cur) {
            atomicAdd(&out[cur * DD + t], s);
            s = 0.f;
            cur = g;
        }
        s += g_agg[(size_t)(base + i) * DD + t];
    }
    atomicAdd(&out[cur * DD + t], s);
}

__global__ void final_kernel(float* __restrict__ out) {
    int idx = blockIdx.x * blockDim.x + threadIdx.x;
    if (idx < NG * DD) out[idx] /= fmaxf((float)g_cnt[idx / DD], 1.0f);
}

extern "C" void kernel_launch(void* const* d_in, const int* in_sizes, int n_in,
                              void* d_out, int out_size) {
    const float* x     = (const float*)d_in[0];
    const int*   ei    = (const int*)d_in[1];    // int32 (JAX x64 disabled)
    const int*   batch = (const int*)d_in[2];    // int32
    const float* W1    = (const float*)d_in[3];
    const float* b1    = (const float*)d_in[4];
    const float* W2    = (const float*)d_in[5];
    const float* b2    = (const float*)d_in[6];
    float*       out   = (float*)d_out;

    const int gemm_blocks  = (NN + 63) / 64;         // 782
    const int scat_blocks  = (NE * 32 + 255) / 256;  // 80000
    const int node4_blocks = (NN * 32 + 255) / 256;

    // degree + dinv (shared by both layers)
    zero_kernel<<<(NN + 255) / 256, 256>>>(out);
    deg_kernel<<<(NE + 255) / 256, 256>>>(ei);
    dinv_kernel<<<(NN + 255) / 256, 256>>>();

    // ---- layer 1 ----
    gemm1_kernel<<<gemm_blocks, 256>>>(x, W1);
    init_agg_kernel<<<node4_blocks, 256>>>(b1);
    scatter_kernel<<<scat_blocks, 256>>>(ei);

    // ---- layer 2 (relu fused into GEMM input read) ----
    gemm2_kernel<<<gemm_blocks, 256>>>(W2);
    init_agg_kernel<<<node4_blocks, 256>>>(b2);
    scatter_kernel<<<scat_blocks, 256>>>(ei);

    // ---- global mean pool ----
    pool_kernel<<<(NN + POOL_CH - 1) / POOL_CH, 128>>>(batch, out);
    final_kernel<<<(NG * DD + 255) / 256, 256>>>(out);
}

// round 9
// speedup vs baseline: 1.8562x; 1.8562x over previous
#include <cuda_runtime.h>

#define NN 50000
#define NE 640000
#define DD 128
#define NG 64

// ---- scratch: __device__ globals only (16B-aligned for float4 access) ----
__device__ __align__(16) float g_h[NN * DD];     // h = X @ W   (25.6 MB)
__device__ __align__(16) float g_agg[NN * DD];   // per-layer aggregation (25.6 MB)
__device__ float g_dinv[NN];
__device__ int   g_deg[NN];
__device__ int   g_row[NN + 1];    // CSR row offsets (by dst)
__device__ int   g_cursor[NN];     // fill cursors
__device__ int   g_esrc[NE];       // CSR column indices (src node per edge)
__device__ float g_enorm[NE];      // precomputed dinv[src]*dinv[dst]
__device__ int   g_cnt[NG];

// ---- zero deg / cnt / out ----
__global__ void zero_kernel(float* __restrict__ out) {
    int i = blockIdx.x * blockDim.x + threadIdx.x;
    if (i < NN) g_deg[i] = 0;
    if (i < NG) g_cnt[i] = 0;
    if (i < NG * DD) out[i] = 0.0f;
}

// ---- degree histogram over dst (edge_index int32, layout [2, NE]) ----
__global__ void deg_kernel(const int* __restrict__ ei) {
    int e = blockIdx.x * blockDim.x + threadIdx.x;
    if (e < NE) atomicAdd(&g_deg[ei[NE + e]], 1);
}

__global__ void dinv_kernel() {
    int i = blockIdx.x * blockDim.x + threadIdx.x;
    if (i < NN) g_dinv[i] = rsqrtf((float)g_deg[i] + 1.0f);
}

// ---- single-block exclusive scan of g_deg -> g_row / g_cursor ----
// 1024 threads, warp-shuffle scan, 49 chunks. ~4us.
__global__ void __launch_bounds__(1024) scan_kernel() {
    __shared__ int wsum[32];
    __shared__ int s_carry;
    int t = threadIdx.x;
    int lane = t & 31, w = t >> 5;
    if (t == 0) s_carry = 0;
    __syncthreads();
    for (int base = 0; base < NN; base += 1024) {
        int idx = base + t;
        int v = (idx < NN) ? g_deg[idx] : 0;
        // inclusive warp scan
        int incl = v;
#pragma unroll
        for (int off = 1; off < 32; off <<= 1) {
            int n = __shfl_up_sync(0xffffffffu, incl, off);
            if (lane >= off) incl += n;
        }
        if (lane == 31) wsum[w] = incl;
        __syncthreads();
        if (w == 0) {
            int ws = wsum[lane];
            int wincl = ws;
#pragma unroll
            for (int off = 1; off < 32; off <<= 1) {
                int n = __shfl_up_sync(0xffffffffu, wincl, off);
                if (lane >= off) wincl += n;
            }
            wsum[lane] = wincl - ws;  // exclusive warp offsets
        }
        __syncthreads();
        int excl = s_carry + wsum[w] + incl - v;
        if (idx < NN) {
            g_row[idx] = excl;
            g_cursor[idx] = excl;
        }
        __syncthreads();
        if (t == 1023) s_carry += wsum[31] + incl;  // total of chunk
        __syncthreads();
    }
    if (t == 0) g_row[NN] = s_carry;
}

// ---- CSR fill: bucket edges by dst, precompute norms ----
__global__ void fill_kernel(const int* __restrict__ ei) {
    int e = blockIdx.x * blockDim.x + threadIdx.x;
    if (e >= NE) return;
    int src = ei[e];
    int dst = ei[NE + e];
    int pos = atomicAdd(&g_cursor[dst], 1);
    g_esrc[pos] = src;
    g_enorm[pos] = g_dinv[src] * g_dinv[dst];
}

// ---- GEMM body: out[N,128] = (RELU? relu(in) : in) @ W[128,128] ----
// 256 threads, 64 rows/block, static smem 48KB, 2 K-chunks of 64.
template <bool RELU>
__device__ __forceinline__ void gemm_body(const float* __restrict__ in,
                                          const float* __restrict__ W,
                                          float* __restrict__ out) {
    __shared__ float Ws[64 * DD];   // 32 KB
    __shared__ float Xs[64 * 64];   // 16 KB
    int t = threadIdx.x;
    int row0 = blockIdx.x * 64;
    int c = t & 31;          // column base: c, c+32, c+64, c+96
    int rb = (t >> 5) * 8;   // 8 rows per thread

    float acc[8][4];
#pragma unroll
    for (int r = 0; r < 8; r++)
#pragma unroll
        for (int j = 0; j < 4; j++) acc[r][j] = 0.f;

#pragma unroll
    for (int kc = 0; kc < 2; kc++) {
        const float4* W4 = (const float4*)(W + kc * 64 * DD);
        float4* Ws4 = (float4*)Ws;
#pragma unroll
        for (int i = 0; i < 8; i++) Ws4[t + 256 * i] = W4[t + 256 * i];

        float4* Xs4 = (float4*)Xs;
#pragma unroll
        for (int i = 0; i < 4; i++) {
            int idx = t + 256 * i;
            int r = idx >> 4, c4 = idx & 15;
            float4 v = make_float4(0.f, 0.f, 0.f, 0.f);
            int row = row0 + r;
            if (row < NN) {
                v = ((const float4*)(in + (size_t)row * DD + kc * 64))[c4];
                if (RELU) {
                    v.x = fmaxf(v.x, 0.f); v.y = fmaxf(v.y, 0.f);
                    v.z = fmaxf(v.z, 0.f); v.w = fmaxf(v.w, 0.f);
                }
            }
            Xs4[idx] = v;
        }
        __syncthreads();

#pragma unroll 4
        for (int k = 0; k < 64; k++) {
            float w0 = Ws[k * DD + c];
            float w1 = Ws[k * DD + c + 32];
            float w2 = Ws[k * DD + c + 64];
            float w3 = Ws[k * DD + c + 96];
#pragma unroll
            for (int r = 0; r < 8; r++) {
                float xv = Xs[(rb + r) * 64 + k];
                acc[r][0] = fmaf(xv, w0, acc[r][0]);
                acc[r][1] = fmaf(xv, w1, acc[r][1]);
                acc[r][2] = fmaf(xv, w2, acc[r][2]);
                acc[r][3] = fmaf(xv, w3, acc[r][3]);
            }
        }
        __syncthreads();
    }

#pragma unroll
    for (int r = 0; r < 8; r++) {
        int row = row0 + rb + r;
        if (row < NN) {
            float* o = out + (size_t)row * DD;
            o[c]      = acc[r][0];
            o[c + 32] = acc[r][1];
            o[c + 64] = acc[r][2];
            o[c + 96] = acc[r][3];
        }
    }
}

__global__ void __launch_bounds__(256) gemm1_kernel(const float* __restrict__ x,
                                                    const float* __restrict__ W) {
    gemm_body<false>(x, W, g_h);
}
__global__ void __launch_bounds__(256) gemm2_kernel(const float* __restrict__ W) {
    gemm_body<true>(g_agg, W, g_h);
}

// ---- pull-based aggregation: warp per dst node ----
// agg[n] = h[n]*dinv_n^2 + b + sum_{e in CSR row n} h[src_e]*norm_e
__global__ void __launch_bounds__(256) gather_kernel(const float* __restrict__ b) {
    int warp = (blockIdx.x * blockDim.x + threadIdx.x) >> 5;
    if (warp >= NN) return;
    int lane = threadIdx.x & 31;

    int r0 = g_row[warp];
    int r1 = g_row[warp + 1];
    float di = g_dinv[warp];
    float s = di * di;

    float4 acc = ((const float4*)(g_h + (size_t)warp * DD))[lane];
    float4 bb = ((const float4*)b)[lane];
    acc.x = fmaf(acc.x, s, bb.x);
    acc.y = fmaf(acc.y, s, bb.y);
    acc.z = fmaf(acc.z, s, bb.z);
    acc.w = fmaf(acc.w, s, bb.w);

    int i = r0;
    for (; i + 4 <= r1; i += 4) {
        int s0 = g_esrc[i], s1 = g_esrc[i + 1], s2 = g_esrc[i + 2], s3 = g_esrc[i + 3];
        float n0 = g_enorm[i], n1 = g_enorm[i + 1], n2 = g_enorm[i + 2], n3 = g_enorm[i + 3];
        float4 h0 = ((const float4*)(g_h + (size_t)s0 * DD))[lane];
        float4 h1 = ((const float4*)(g_h + (size_t)s1 * DD))[lane];
        float4 h2 = ((const float4*)(g_h + (size_t)s2 * DD))[lane];
        float4 h3 = ((const float4*)(g_h + (size_t)s3 * DD))[lane];
        acc.x = fmaf(h0.x, n0, fmaf(h1.x, n1, fmaf(h2.x, n2, fmaf(h3.x, n3, acc.x))));
        acc.y = fmaf(h0.y, n0, fmaf(h1.y, n1, fmaf(h2.y, n2, fmaf(h3.y, n3, acc.y))));
        acc.z = fmaf(h0.z, n0, fmaf(h1.z, n1, fmaf(h2.z, n2, fmaf(h3.z, n3, acc.z))));
        acc.w = fmaf(h0.w, n0, fmaf(h1.w, n1, fmaf(h2.w, n2, fmaf(h3.w, n3, acc.w))));
    }
    for (; i < r1; i++) {
        int sidx = g_esrc[i];
        float nn = g_enorm[i];
        float4 h = ((const float4*)(g_h + (size_t)sidx * DD))[lane];
        acc.x = fmaf(h.x, nn, acc.x);
        acc.y = fmaf(h.y, nn, acc.y);
        acc.z = fmaf(h.z, nn, acc.z);
        acc.w = fmaf(h.w, nn, acc.w);
    }

    ((float4*)(g_agg + (size_t)warp * DD))[lane] = acc;
}

// ---- segmented mean pool (batch sorted): 128 thr = channels, 256 nodes/block ----
#define POOL_CH 256
__global__ void pool_kernel(const int* __restrict__ batch, float* __restrict__ out) {
    __shared__ int sb[POOL_CH];
    int t = threadIdx.x;  // 128
    int base = blockIdx.x * POOL_CH;
    int nn = min(POOL_CH, NN - base);
    for (int i = t; i < nn; i += 128) sb[i] = batch[base + i];
    __syncthreads();
    for (int i = t; i < nn; i += 128) atomicAdd(&g_cnt[sb[i]], 1);

    float s = 0.f;
    int cur = sb[0];
    for (int i = 0; i < nn; i++) {
        int g = sb[i];
        if (g != cur) {
            atomicAdd(&out[cur * DD + t], s);
            s = 0.f;
            cur = g;
        }
        s += g_agg[(size_t)(base + i) * DD + t];
    }
    atomicAdd(&out[cur * DD + t], s);
}

__global__ void final_kernel(float* __restrict__ out) {
    int idx = blockIdx.x * blockDim.x + threadIdx.x;
    if (idx < NG * DD) out[idx] /= fmaxf((float)g_cnt[idx / DD], 1.0f);
}

extern "C" void kernel_launch(void* const* d_in, const int* in_sizes, int n_in,
                              void* d_out, int out_size) {
    const float* x     = (const float*)d_in[0];
    const int*   ei    = (const int*)d_in[1];    // int32
    const int*   batch = (const int*)d_in[2];    // int32
    const float* W1    = (const float*)d_in[3];
    const float* b1    = (const float*)d_in[4];
    const float* W2    = (const float*)d_in[5];
    const float* b2    = (const float*)d_in[6];
    float*       out   = (float*)d_out;

    const int gemm_blocks   = (NN + 63) / 64;          // 782
    const int gather_blocks = (NN * 32 + 255) / 256;   // warp per node
    const int edge_blocks   = (NE + 255) / 256;

    // graph preprocessing (shared by both layers)
    zero_kernel<<<(NN + 255) / 256, 256>>>(out);
    deg_kernel<<<edge_blocks, 256>>>(ei);
    dinv_kernel<<<(NN + 255) / 256, 256>>>();
    scan_kernel<<<1, 1024>>>();
    fill_kernel<<<edge_blocks, 256>>>(ei);

    // ---- layer 1 ----
    gemm1_kernel<<<gemm_blocks, 256>>>(x, W1);
    gather_kernel<<<gather_blocks, 256>>>(b1);

    // ---- layer 2 (relu fused into GEMM input read) ----
    gemm2_kernel<<<gemm_blocks, 256>>>(W2);
    gather_kernel<<<gather_blocks, 256>>>(b2);

    // ---- global mean pool ----
    pool_kernel<<<(NN + POOL_CH - 1) / POOL_CH, 128>>>(batch, out);
    final_kernel<<<(NG * DD + 255) / 256, 256>>>(out);
}

// round 10
// speedup vs baseline: 2.0651x; 1.1125x over previous
#include <cuda_runtime.h>

#define NN 50000
#define NE 640000
#define DD 128
#define NG 64
#define SCAN_BLOCKS 49   // ceil(NN/1024)

// ---- packed fp32x2 helpers (Blackwell FFMA2: only reachable via PTX) ----
#define FFMA2(d, a, b, cc) \
    asm("fma.rn.f32x2 %0, %1, %2, %3;" : "=l"(d) : "l"(a), "l"(b), "l"(cc))
#define PACK2(d, lo, hi) \
    asm("mov.b64 %0, {%1, %2};" : "=l"(d) : "r"(lo), "r"(hi))
#define UNPACK2(lo, hi, s) \
    asm("mov.b64 {%0, %1}, %2;" : "=r"(lo), "=r"(hi) : "l"(s))

// ---- scratch: __device__ globals only (16B-aligned for float4 access) ----
__device__ __align__(16) float g_h[NN * DD];     // h = X @ W   (25.6 MB)
__device__ __align__(16) float g_agg[NN * DD];   // per-layer aggregation (25.6 MB)
__device__ float g_dinv[NN];
__device__ int   g_deg[NN];
__device__ int   g_row[NN + 1];    // CSR row offsets (by dst)
__device__ int   g_cursor[NN];     // fill cursors
__device__ int   g_bsum[64];       // per-block scan totals
__device__ int   g_esrc[NE];       // CSR column indices (src node per edge)
__device__ float g_enorm[NE];      // precomputed dinv[src]*dinv[dst]
__device__ int   g_cnt[NG];

// ---- zero deg / cnt / out ----
__global__ void zero_kernel(float* __restrict__ out) {
    int i = blockIdx.x * blockDim.x + threadIdx.x;
    if (i < NN) g_deg[i] = 0;
    if (i < NG) g_cnt[i] = 0;
    if (i < NG * DD) out[i] = 0.0f;
}

// ---- degree histogram over dst (edge_index int32, layout [2, NE]) ----
__global__ void deg_kernel(const int* __restrict__ ei) {
    int e = blockIdx.x * blockDim.x + threadIdx.x;
    if (e < NE) atomicAdd(&g_deg[ei[NE + e]], 1);
}

// ---- hierarchical exclusive scan of g_deg ----
// scan1: each of 49 blocks scans its 1024-chunk, writes local-exclusive to
// g_row and block total to g_bsum. Also computes dinv (fused).
__global__ void __launch_bounds__(1024) scan1_kernel() {
    __shared__ int wsum[32];
    int t = threadIdx.x, lane = t & 31, w = t >> 5;
    int idx = blockIdx.x * 1024 + t;
    int v = (idx < NN) ? g_deg[idx] : 0;
    int incl = v;
#pragma unroll
    for (int off = 1; off < 32; off <<= 1) {
        int n = __shfl_up_sync(0xffffffffu, incl, off);
        if (lane >= off) incl += n;
    }
    if (lane == 31) wsum[w] = incl;
    __syncthreads();
    if (w == 0) {
        int ws = wsum[lane];
        int wi = ws;
#pragma unroll
        for (int off = 1; off < 32; off <<= 1) {
            int n = __shfl_up_sync(0xffffffffu, wi, off);
            if (lane >= off) wi += n;
        }
        wsum[lane] = wi - ws;  // exclusive warp offsets
    }
    __syncthreads();
    if (idx < NN) {
        g_row[idx] = wsum[w] + incl - v;               // local exclusive
        g_dinv[idx] = rsqrtf((float)v + 1.0f);
    }
    if (t == 1023) g_bsum[blockIdx.x] = wsum[31] + incl;  // block total
}

// scan2: exclusive scan of the 49 block totals (single tiny block).
__global__ void scan2_kernel() {
    __shared__ int s[64];
    int t = threadIdx.x;  // 64
    int v = (t < SCAN_BLOCKS) ? g_bsum[t] : 0;
    s[t] = v;
    __syncthreads();
    for (int off = 1; off < 64; off <<= 1) {
        int add = (t >= off) ? s[t - off] : 0;
        __syncthreads();
        s[t] += add;
        __syncthreads();
    }
    if (t < SCAN_BLOCKS) g_bsum[t] = s[t] - v;  // exclusive block offsets
}

// scan3: add block offsets, init cursors.
__global__ void scan3_kernel() {
    int i = blockIdx.x * blockDim.x + threadIdx.x;
    if (i < NN) {
        int val = g_row[i] + g_bsum[i >> 10];
        g_row[i] = val;
        g_cursor[i] = val;
    }
    if (i == 0) g_row[NN] = NE;
}

// ---- CSR fill: bucket edges by dst, precompute norms ----
__global__ void fill_kernel(const int* __restrict__ ei) {
    int e = blockIdx.x * blockDim.x + threadIdx.x;
    if (e >= NE) return;
    int src = ei[e];
    int dst = ei[NE + e];
    int pos = atomicAdd(&g_cursor[dst], 1);
    g_esrc[pos] = src;
    g_enorm[pos] = g_dinv[src] * g_dinv[dst];
}

// ---- GEMM body: out[N,128] = (RELU? relu(in) : in) @ W[128,128] ----
// 256 threads, 64 rows/block, 48KB static smem, 2 K-chunks of 64.
// FFMA2 (packed fp32x2): thread computes 4 row-pairs x 4 cols.
// Xs stored k-major transposed with XOR swizzle e=(2k)&24 (bits 3..4 only,
// commutes with the +2p in-pair offset -> pair-aligned LDS.64, broadcast reads).
template <bool RELU>
__device__ __forceinline__ void gemm_body(const float* __restrict__ in,
                                          const float* __restrict__ W,
                                          float* __restrict__ out) {
    __shared__ __align__(16) float Ws[64 * DD];   // 32 KB
    __shared__ __align__(16) float Xs[64 * 64];   // 16 KB, [k][row^swz]
    int t = threadIdx.x;
    int row0 = blockIdx.x * 64;
    int c = t & 31;          // column base: c, c+32, c+64, c+96
    int rb = (t >> 5) * 8;   // 8 rows (4 pairs) per thread

    unsigned long long accp[4][4];  // [row pair][col j], packed (lo=row, hi=row+1)
#pragma unroll
    for (int p = 0; p < 4; p++)
#pragma unroll
        for (int j = 0; j < 4; j++) accp[p][j] = 0ULL;

#pragma unroll
    for (int kc = 0; kc < 2; kc++) {
        // load W rows [kc*64, kc*64+64), all 128 cols: 2048 float4
        const float4* W4 = (const float4*)(W + kc * 64 * DD);
        float4* Ws4 = (float4*)Ws;
#pragma unroll
        for (int i = 0; i < 8; i++) Ws4[t + 256 * i] = W4[t + 256 * i];

        // load X tile transposed: 64 rows x 64 k. Each thread: 1 float4 row-chunk
        // -> 4 scalar stores at k-major swizzled addresses (4-way conflict, load
        // phase only).
#pragma unroll
        for (int i = 0; i < 4; i++) {
            int idx = t + 256 * i;
            int r = idx >> 4, c4 = idx & 15;
            float4 v = make_float4(0.f, 0.f, 0.f, 0.f);
            int row = row0 + r;
            if (row < NN) {
                v = ((const float4*)(in + (size_t)row * DD + kc * 64))[c4];
                if (RELU) {
                    v.x = fmaxf(v.x, 0.f); v.y = fmaxf(v.y, 0.f);
                    v.z = fmaxf(v.z, 0.f); v.w = fmaxf(v.w, 0.f);
                }
            }
            int k0 = c4 * 4;
            Xs[(k0 + 0) * 64 + (r ^ ((2 * (k0 + 0)) & 24))] = v.x;
            Xs[(k0 + 1) * 64 + (r ^ ((2 * (k0 + 1)) & 24))] = v.y;
            Xs[(k0 + 2) * 64 + (r ^ ((2 * (k0 + 2)) & 24))] = v.z;
            Xs[(k0 + 3) * 64 + (r ^ ((2 * (k0 + 3)) & 24))] = v.w;
        }
        __syncthreads();

#pragma unroll 4
        for (int k = 0; k < 64; k++) {
            int e = (2 * k) & 24;
            const unsigned long long* xrow =
                (const unsigned long long*)&Xs[k * 64 + (rb ^ e)];
            unsigned long long xp0 = xrow[0];
            unsigned long long xp1 = xrow[1];
            unsigned long long xp2 = xrow[2];
            unsigned long long xp3 = xrow[3];

            unsigned int w0 = __float_as_uint(Ws[k * DD + c]);
            unsigned int w1 = __float_as_uint(Ws[k * DD + c + 32]);
            unsigned int w2 = __float_as_uint(Ws[k * DD + c + 64]);
            unsigned int w3 = __float_as_uint(Ws[k * DD + c + 96]);
            unsigned long long wp0, wp1, wp2, wp3;
            PACK2(wp0, w0, w0);
            PACK2(wp1, w1, w1);
            PACK2(wp2, w2, w2);
            PACK2(wp3, w3, w3);

            FFMA2(accp[0][0], xp0, wp0, accp[0][0]);
            FFMA2(accp[0][1], xp0, wp1, accp[0][1]);
            FFMA2(accp[0][2], xp0, wp2, accp[0][2]);
            FFMA2(accp[0][3], xp0, wp3, accp[0][3]);
            FFMA2(accp[1][0], xp1, wp0, accp[1][0]);
            FFMA2(accp[1][1], xp1, wp1, accp[1][1]);
            FFMA2(accp[1][2], xp1, wp2, accp[1][2]);
            FFMA2(accp[1][3], xp1, wp3, accp[1][3]);
            FFMA2(accp[2][0], xp2, wp0, accp[2][0]);
            FFMA2(accp[2][1], xp2, wp1, accp[2][1]);
            FFMA2(accp[2][2], xp2, wp2, accp[2][2]);
            FFMA2(accp[2][3], xp2, wp3, accp[2][3]);
            FFMA2(accp[3][0], xp3, wp0, accp[3][0]);
            FFMA2(accp[3][1], xp3, wp1, accp[3][1]);
            FFMA2(accp[3][2], xp3, wp2, accp[3][2]);
            FFMA2(accp[3][3], xp3, wp3, accp[3][3]);
        }
        __syncthreads();
    }

#pragma unroll
    for (int p = 0; p < 4; p++) {
        int row = row0 + rb + 2 * p;  // even; row+1 valid iff row < NN (NN even)
        if (row < NN) {
            float* o0 = out + (size_t)row * DD;
            float* o1 = o0 + DD;
#pragma unroll
            for (int j = 0; j < 4; j++) {
                unsigned int lo, hi;
                UNPACK2(lo, hi, accp[p][j]);
                o0[c + 32 * j] = __uint_as_float(lo);
                o1[c + 32 * j] = __uint_as_float(hi);
            }
        }
    }
}

__global__ void __launch_bounds__(256) gemm1_kernel(const float* __restrict__ x,
                                                    const float* __restrict__ W) {
    gemm_body<false>(x, W, g_h);
}
__global__ void __launch_bounds__(256) gemm2_kernel(const float* __restrict__ W) {
    gemm_body<true>(g_agg, W, g_h);
}

// ---- pull-based aggregation: warp per dst node ----
// agg[n] = h[n]*dinv_n^2 + b + sum_{e in CSR row n} h[src_e]*norm_e
__global__ void __launch_bounds__(256) gather_kernel(const float* __restrict__ b) {
    int warp = (blockIdx.x * blockDim.x + threadIdx.x) >> 5;
    if (warp >= NN) return;
    int lane = threadIdx.x & 31;

    int r0 = g_row[warp];
    int r1 = g_row[warp + 1];
    float di = g_dinv[warp];
    float s = di * di;

    float4 acc = ((const float4*)(g_h + (size_t)warp * DD))[lane];
    float4 bb = ((const float4*)b)[lane];
    acc.x = fmaf(acc.x, s, bb.x);
    acc.y = fmaf(acc.y, s, bb.y);
    acc.z = fmaf(acc.z, s, bb.z);
    acc.w = fmaf(acc.w, s, bb.w);

    int i = r0;
    for (; i + 4 <= r1; i += 4) {
        int s0 = g_esrc[i], s1 = g_esrc[i + 1], s2 = g_esrc[i + 2], s3 = g_esrc[i + 3];
        float n0 = g_enorm[i], n1 = g_enorm[i + 1], n2 = g_enorm[i + 2], n3 = g_enorm[i + 3];
        float4 h0 = ((const float4*)(g_h + (size_t)s0 * DD))[lane];
        float4 h1 = ((const float4*)(g_h + (size_t)s1 * DD))[lane];
        float4 h2 = ((const float4*)(g_h + (size_t)s2 * DD))[lane];
        float4 h3 = ((const float4*)(g_h + (size_t)s3 * DD))[lane];
        acc.x = fmaf(h0.x, n0, fmaf(h1.x, n1, fmaf(h2.x, n2, fmaf(h3.x, n3, acc.x))));
        acc.y = fmaf(h0.y, n0, fmaf(h1.y, n1, fmaf(h2.y, n2, fmaf(h3.y, n3, acc.y))));
        acc.z = fmaf(h0.z, n0, fmaf(h1.z, n1, fmaf(h2.z, n2, fmaf(h3.z, n3, acc.z))));
        acc.w = fmaf(h0.w, n0, fmaf(h1.w, n1, fmaf(h2.w, n2, fmaf(h3.w, n3, acc.w))));
    }
    for (; i < r1; i++) {
        int sidx = g_esrc[i];
        float nn = g_enorm[i];
        float4 h = ((const float4*)(g_h + (size_t)sidx * DD))[lane];
        acc.x = fmaf(h.x, nn, acc.x);
        acc.y = fmaf(h.y, nn, acc.y);
        acc.z = fmaf(h.z, nn, acc.z);
        acc.w = fmaf(h.w, nn, acc.w);
    }

    ((float4*)(g_agg + (size_t)warp * DD))[lane] = acc;
}

// ---- segmented mean pool (batch sorted): 128 thr = channels, 256 nodes/block ----
#define POOL_CH 256
__global__ void pool_kernel(const int* __restrict__ batch, float* __restrict__ out) {
    __shared__ int sb[POOL_CH];
    int t = threadIdx.x;  // 128
    int base = blockIdx.x * POOL_CH;
    int nn = min(POOL_CH, NN - base);
    for (int i = t; i < nn; i += 128) sb[i] = batch[base + i];
    __syncthreads();
    for (int i = t; i < nn; i += 128) atomicAdd(&g_cnt[sb[i]], 1);

    float s = 0.f;
    int cur = sb[0];
    for (int i = 0; i < nn; i++) {
        int g = sb[i];
        if (g != cur) {
            atomicAdd(&out[cur * DD + t], s);
            s = 0.f;
            cur = g;
        }
        s += g_agg[(size_t)(base + i) * DD + t];
    }
    atomicAdd(&out[cur * DD + t], s);
}

__global__ void final_kernel(float* __restrict__ out) {
    int idx = blockIdx.x * blockDim.x + threadIdx.x;
    if (idx < NG * DD) out[idx] /= fmaxf((float)g_cnt[idx / DD], 1.0f);
}

extern "C" void kernel_launch(void* const* d_in, const int* in_sizes, int n_in,
                              void* d_out, int out_size) {
    const float* x     = (const float*)d_in[0];
    const int*   ei    = (const int*)d_in[1];    // int32
    const int*   batch = (const int*)d_in[2];    // int32
    const float* W1    = (const float*)d_in[3];
    const float* b1    = (const float*)d_in[4];
    const float* W2    = (const float*)d_in[5];
    const float* b2    = (const float*)d_in[6];
    float*       out   = (float*)d_out;

    const int gemm_blocks   = (NN + 63) / 64;          // 782
    const int gather_blocks = (NN * 32 + 255) / 256;   // warp per node
    const int edge_blocks   = (NE + 255) / 256;

    // graph preprocessing (shared by both layers)
    zero_kernel<<<(NN + 255) / 256, 256>>>(out);
    deg_kernel<<<edge_blocks, 256>>>(ei);
    scan1_kernel<<<SCAN_BLOCKS, 1024>>>();
    scan2_kernel<<<1, 64>>>();
    scan3_kernel<<<(NN + 255) / 256, 256>>>();
    fill_kernel<<<edge_blocks, 256>>>(ei);

    // ---- layer 1 ----
    gemm1_kernel<<<gemm_blocks, 256>>>(x, W1);
    gather_kernel<<<gather_blocks, 256>>>(b1);

    // ---- layer 2 (relu fused into GEMM input read) ----
    gemm2_kernel<<<gemm_blocks, 256>>>(W2);
    gather_kernel<<<gather_blocks, 256>>>(b2);

    // ---- global mean pool ----
    pool_kernel<<<(NN + POOL_CH - 1) / POOL_CH, 128>>>(batch, out);
    final_kernel<<<(NG * DD + 255) / 256, 256>>>(out);
}

// round 15
// speedup vs baseline: 2.8082x; 1.3598x over previous
#include <cuda_runtime.h>

#define NN 50000
#define NE 640000
#define DD 128
#define NG 64
#define SCAN_BLOCKS 49   // ceil(NN/1024)

// ---- packed fp32x2 helpers (Blackwell FFMA2: only reachable via PTX) ----
#define FFMA2(d, a, b, cc) \
    asm("fma.rn.f32x2 %0, %1, %2, %3;" : "=l"(d) : "l"(a), "l"(b), "l"(cc))
#define PACK2(d, lo, hi) \
    asm("mov.b64 %0, {%1, %2};" : "=l"(d) : "r"(lo), "r"(hi))
#define UNPACK2(lo, hi, s) \
    asm("mov.b64 {%0, %1}, %2;" : "=r"(lo), "=r"(hi) : "l"(s))

// ---- scratch: __device__ globals only (16B-aligned for float4 access) ----
__device__ __align__(16) float g_h[NN * DD];     // h = X @ W   (25.6 MB)
__device__ __align__(16) float g_agg[NN * DD];   // layer-1 aggregation (25.6 MB)
__device__ float g_dinv[NN];
__device__ int   g_deg[NN];
__device__ int   g_row[NN + 1];    // CSR row offsets (by dst)
__device__ int   g_cursor[NN];     // fill cursors
__device__ int   g_bsum[64];       // per-block scan totals
__device__ __align__(16) int2 g_edge[NE];  // {src, norm-as-int} per CSR slot
__device__ int   g_cnt[NG];

// ---- zero deg / cnt / out ----
__global__ void zero_kernel(float* __restrict__ out) {
    int i = blockIdx.x * blockDim.x + threadIdx.x;
    if (i < NN) g_deg[i] = 0;
    if (i < NG) g_cnt[i] = 0;
    if (i < NG * DD) out[i] = 0.0f;
}

// ---- degree histogram over dst + per-graph node counts ----
__global__ void deg_kernel(const int* __restrict__ ei, const int* __restrict__ batch) {
    int e = blockIdx.x * blockDim.x + threadIdx.x;
    if (e < NE) atomicAdd(&g_deg[ei[NE + e]], 1);
    if (e < NN) atomicAdd(&g_cnt[batch[e]], 1);
}

// ---- hierarchical exclusive scan of g_deg (3 kernels) ----
__global__ void __launch_bounds__(1024) scan1_kernel() {
    __shared__ int wsum[32];
    int t = threadIdx.x, lane = t & 31, w = t >> 5;
    int idx = blockIdx.x * 1024 + t;
    int v = (idx < NN) ? g_deg[idx] : 0;
    int incl = v;
#pragma unroll
    for (int off = 1; off < 32; off <<= 1) {
        int n = __shfl_up_sync(0xffffffffu, incl, off);
        if (lane >= off) incl += n;
    }
    if (lane == 31) wsum[w] = incl;
    __syncthreads();
    if (w == 0) {
        int ws = wsum[lane];
        int wi = ws;
#pragma unroll
        for (int off = 1; off < 32; off <<= 1) {
            int n = __shfl_up_sync(0xffffffffu, wi, off);
            if (lane >= off) wi += n;
        }
        wsum[lane] = wi - ws;  // exclusive warp offsets
    }
    __syncthreads();
    if (idx < NN) {
        g_row[idx] = wsum[w] + incl - v;               // local exclusive
        g_dinv[idx] = rsqrtf((float)v + 1.0f);
    }
    if (t == 1023) g_bsum[blockIdx.x] = wsum[31] + incl;  // block total
}

__global__ void scan2_kernel() {
    __shared__ int s[64];
    int t = threadIdx.x;  // 64
    int v = (t < SCAN_BLOCKS) ? g_bsum[t] : 0;
    s[t] = v;
    __syncthreads();
    for (int off = 1; off < 64; off <<= 1) {
        int add = (t >= off) ? s[t - off] : 0;
        __syncthreads();
        s[t] += add;
        __syncthreads();
    }
    if (t < SCAN_BLOCKS) g_bsum[t] = s[t] - v;  // exclusive block offsets
}

__global__ void scan3_kernel() {
    int i = blockIdx.x * blockDim.x + threadIdx.x;
    if (i < NN) {
        int val = g_row[i] + g_bsum[i >> 10];
        g_row[i] = val;
        g_cursor[i] = val;
    }
    if (i == 0) g_row[NN] = NE;
}

// ---- CSR fill: bucket edges by dst, pack {src, norm} in one 8B store ----
__global__ void fill_kernel(const int* __restrict__ ei) {
    int e = blockIdx.x * blockDim.x + threadIdx.x;
    if (e >= NE) return;
    int src = ei[e];
    int dst = ei[NE + e];
    int pos = atomicAdd(&g_cursor[dst], 1);
    g_edge[pos] = make_int2(src, __float_as_int(g_dinv[src] * g_dinv[dst]));
}

// ---- GEMM body: out[N,128] = (RELU? relu(in) : in) @ W[128,128] ----
// 256 threads, 64 rows/block, 48KB static smem, 2 K-chunks of 64, FFMA2.
template <bool RELU>
__device__ __forceinline__ void gemm_body(const float* __restrict__ in,
                                          const float* __restrict__ W,
                                          float* __restrict__ out) {
    __shared__ __align__(16) float Ws[64 * DD];   // 32 KB
    __shared__ __align__(16) float Xs[64 * 64];   // 16 KB, [k][row^swz]
    int t = threadIdx.x;
    int row0 = blockIdx.x * 64;
    int c = t & 31;
    int rb = (t >> 5) * 8;

    unsigned long long accp[4][4];
#pragma unroll
    for (int p = 0; p < 4; p++)
#pragma unroll
        for (int j = 0; j < 4; j++) accp[p][j] = 0ULL;

#pragma unroll
    for (int kc = 0; kc < 2; kc++) {
        const float4* W4 = (const float4*)(W + kc * 64 * DD);
        float4* Ws4 = (float4*)Ws;
#pragma unroll
        for (int i = 0; i < 8; i++) Ws4[t + 256 * i] = W4[t + 256 * i];

#pragma unroll
        for (int i = 0; i < 4; i++) {
            int idx = t + 256 * i;
            int r = idx >> 4, c4 = idx & 15;
            float4 v = make_float4(0.f, 0.f, 0.f, 0.f);
            int row = row0 + r;
            if (row < NN) {
                v = ((const float4*)(in + (size_t)row * DD + kc * 64))[c4];
                if (RELU) {
                    v.x = fmaxf(v.x, 0.f); v.y = fmaxf(v.y, 0.f);
                    v.z = fmaxf(v.z, 0.f); v.w = fmaxf(v.w, 0.f);
                }
            }
            int k0 = c4 * 4;
            Xs[(k0 + 0) * 64 + (r ^ ((2 * (k0 + 0)) & 24))] = v.x;
            Xs[(k0 + 1) * 64 + (r ^ ((2 * (k0 + 1)) & 24))] = v.y;
            Xs[(k0 + 2) * 64 + (r ^ ((2 * (k0 + 2)) & 24))] = v.z;
            Xs[(k0 + 3) * 64 + (r ^ ((2 * (k0 + 3)) & 24))] = v.w;
        }
        __syncthreads();

#pragma unroll 4
        for (int k = 0; k < 64; k++) {
            int e = (2 * k) & 24;
            const unsigned long long* xrow =
                (const unsigned long long*)&Xs[k * 64 + (rb ^ e)];
            unsigned long long xp0 = xrow[0];
            unsigned long long xp1 = xrow[1];
            unsigned long long xp2 = xrow[2];
            unsigned long long xp3 = xrow[3];

            unsigned int w0 = __float_as_uint(Ws[k * DD + c]);
            unsigned int w1 = __float_as_uint(Ws[k * DD + c + 32]);
            unsigned int w2 = __float_as_uint(Ws[k * DD + c + 64]);
            unsigned int w3 = __float_as_uint(Ws[k * DD + c + 96]);
            unsigned long long wp0, wp1, wp2, wp3;
            PACK2(wp0, w0, w0);
            PACK2(wp1, w1, w1);
            PACK2(wp2, w2, w2);
            PACK2(wp3, w3, w3);

            FFMA2(accp[0][0], xp0, wp0, accp[0][0]);
            FFMA2(accp[0][1], xp0, wp1, accp[0][1]);
            FFMA2(accp[0][2], xp0, wp2, accp[0][2]);
            FFMA2(accp[0][3], xp0, wp3, accp[0][3]);
            FFMA2(accp[1][0], xp1, wp0, accp[1][0]);
            FFMA2(accp[1][1], xp1, wp1, accp[1][1]);
            FFMA2(accp[1][2], xp1, wp2, accp[1][2]);
            FFMA2(accp[1][3], xp1, wp3, accp[1][3]);
            FFMA2(accp[2][0], xp2, wp0, accp[2][0]);
            FFMA2(accp[2][1], xp2, wp1, accp[2][1]);
            FFMA2(accp[2][2], xp2, wp2, accp[2][2]);
            FFMA2(accp[2][3], xp2, wp3, accp[2][3]);
            FFMA2(accp[3][0], xp3, wp0, accp[3][0]);
            FFMA2(accp[3][1], xp3, wp1, accp[3][1]);
            FFMA2(accp[3][2], xp3, wp2, accp[3][2]);
            FFMA2(accp[3][3], xp3, wp3, accp[3][3]);
        }
        __syncthreads();
    }

#pragma unroll
    for (int p = 0; p < 4; p++) {
        int row = row0 + rb + 2 * p;
        if (row < NN) {
            float* o0 = out + (size_t)row * DD;
            float* o1 = o0 + DD;
#pragma unroll
            for (int j = 0; j < 4; j++) {
                unsigned int lo, hi;
                UNPACK2(lo, hi, accp[p][j]);
                o0[c + 32 * j] = __uint_as_float(lo);
                o1[c + 32 * j] = __uint_as_float(hi);
            }
        }
    }
}

__global__ void __launch_bounds__(256) gemm1_kernel(const float* __restrict__ x,
                                                    const float* __restrict__ W) {
    gemm_body<false>(x, W, g_h);
}
__global__ void __launch_bounds__(256) gemm2_kernel(const float* __restrict__ W) {
    gemm_body<true>(g_agg, W, g_h);
}

// ---- shared gather core: returns this node's aggregated float4 for `lane` ----
__device__ __forceinline__ float4 gather_node(int node, int lane,
                                              const float* __restrict__ b) {
    int r0 = g_row[node];
    int r1 = g_row[node + 1];
    float di = g_dinv[node];
    float s = di * di;

    float4 acc = ((const float4*)(g_h + (size_t)node * DD))[lane];
    float4 bb = ((const float4*)b)[lane];
    acc.x = fmaf(acc.x, s, bb.x);
    acc.y = fmaf(acc.y, s, bb.y);
    acc.z = fmaf(acc.z, s, bb.z);
    acc.w = fmaf(acc.w, s, bb.w);

    int i = r0;
    for (; i + 4 <= r1; i += 4) {
        int2 e0 = g_edge[i], e1 = g_edge[i + 1], e2 = g_edge[i + 2], e3 = g_edge[i + 3];
        float n0 = __int_as_float(e0.y), n1 = __int_as_float(e1.y);
        float n2 = __int_as_float(e2.y), n3 = __int_as_float(e3.y);
        float4 h0 = ((const float4*)(g_h + (size_t)e0.x * DD))[lane];
        float4 h1 = ((const float4*)(g_h + (size_t)e1.x * DD))[lane];
        float4 h2 = ((const float4*)(g_h + (size_t)e2.x * DD))[lane];
        float4 h3 = ((const float4*)(g_h + (size_t)e3.x * DD))[lane];
        acc.x = fmaf(h0.x, n0, fmaf(h1.x, n1, fmaf(h2.x, n2, fmaf(h3.x, n3, acc.x))));
        acc.y = fmaf(h0.y, n0, fmaf(h1.y, n1, fmaf(h2.y, n2, fmaf(h3.y, n3, acc.y))));
        acc.z = fmaf(h0.z, n0, fmaf(h1.z, n1, fmaf(h2.z, n2, fmaf(h3.z, n3, acc.z))));
        acc.w = fmaf(h0.w, n0, fmaf(h1.w, n1, fmaf(h2.w, n2, fmaf(h3.w, n3, acc.w))));
    }
    for (; i < r1; i++) {
        int2 e = g_edge[i];
        float nn = __int_as_float(e.y);
        float4 h = ((const float4*)(g_h + (size_t)e.x * DD))[lane];
        acc.x = fmaf(h.x, nn, acc.x);
        acc.y = fmaf(h.y, nn, acc.y);
        acc.z = fmaf(h.z, nn, acc.z);
        acc.w = fmaf(h.w, nn, acc.w);
    }
    return acc;
}

// ---- layer-1 gather: writes g_agg ----
__global__ void __launch_bounds__(256) gather1_kernel(const float* __restrict__ b) {
    int node = (blockIdx.x * blockDim.x + threadIdx.x) >> 5;
    if (node >= NN) return;
    int lane = threadIdx.x & 31;
    float4 acc = gather_node(node, lane, b);
    ((float4*)(g_agg + (size_t)node * DD))[lane] = acc;
}

// ---- layer-2 gather fused with global mean pool (sums only; final divides) ----
// Block = 8 warps = 8 consecutive nodes; batch sorted -> usually one graph per
// block: pre-reduce in SMEM, then 128 global atomics; else per-warp atomics.
__global__ void __launch_bounds__(256) gather2_pool_kernel(const float* __restrict__ b,
                                                           const int* __restrict__ batch,
                                                           float* __restrict__ out) {
    __shared__ int sg[8];
    __shared__ float sacc[DD];
    int t = threadIdx.x;
    int w = t >> 5, lane = t & 31;
    int node = blockIdx.x * 8 + w;          // NN = 6250*8, always in range

    float4 acc = gather_node(node, lane, b);
    int g = batch[node];
    if (lane == 0) sg[w] = g;
    if (t < DD) sacc[t] = 0.f;
    __syncthreads();
    int uni = __syncthreads_and(sg[w] == sg[0]);

    if (uni) {
        float* sa = sacc + lane * 4;
        atomicAdd(sa + 0, acc.x);
        atomicAdd(sa + 1, acc.y);
        atomicAdd(sa + 2, acc.z);
        atomicAdd(sa + 3, acc.w);
        __syncthreads();
        if (t < DD) atomicAdd(&out[sg[0] * DD + t], sacc[t]);
    } else {
        float* o = out + g * DD + lane * 4;
        atomicAdd(o + 0, acc.x);
        atomicAdd(o + 1, acc.y);
        atomicAdd(o + 2, acc.z);
        atomicAdd(o + 3, acc.w);
    }
}

__global__ void final_kernel(float* __restrict__ out) {
    int idx = blockIdx.x * blockDim.x + threadIdx.x;
    if (idx < NG * DD) out[idx] /= fmaxf((float)g_cnt[idx / DD], 1.0f);
}

extern "C" void kernel_launch(void* const* d_in, const int* in_sizes, int n_in,
                              void* d_out, int out_size) {
    const float* x     = (const float*)d_in[0];
    const int*   ei    = (const int*)d_in[1];    // int32
    const int*   batch = (const int*)d_in[2];    // int32
    const float* W1    = (const float*)d_in[3];
    const float* b1    = (const float*)d_in[4];
    const float* W2    = (const float*)d_in[5];
    const float* b2    = (const float*)d_in[6];
    float*       out   = (float*)d_out;

    // one-time side stream + fork/join events (created outside any capture,
    // on the first (correctness) invocation; reused identically every call)
    static cudaStream_t s2 = nullptr;
    static cudaEvent_t evFork = nullptr, evJoin = nullptr;
    if (!s2) {
        cudaStreamCreateWithFlags(&s2, cudaStreamNonBlocking);
        cudaEventCreateWithFlags(&evFork, cudaEventDisableTiming);
        cudaEventCreateWithFlags(&evJoin, cudaEventDisableTiming);
    }

    const int gemm_blocks   = (NN + 63) / 64;          // 782
    const int gather_blocks = (NN * 32 + 255) / 256;   // warp per node
    const int edge_blocks   = (NE + 255) / 256;

    // ---- fork: gemm1 on side stream, CSR build on main stream ----
    cudaEventRecord(evFork, 0);
    cudaStreamWaitEvent(s2, evFork, 0);
    gemm1_kernel<<<gemm_blocks, 256, 0, s2>>>(x, W1);
    cudaEventRecord(evJoin, s2);

    zero_kernel<<<(NN + 255) / 256, 256>>>(out);
    deg_kernel<<<edge_blocks, 256>>>(ei, batch);
    scan1_kernel<<<SCAN_BLOCKS, 1024>>>();
    scan2_kernel<<<1, 64>>>();
    scan3_kernel<<<(NN + 255) / 256, 256>>>();
    fill_kernel<<<edge_blocks, 256>>>(ei);

    // ---- join, then layer 1 aggregation ----
    cudaStreamWaitEvent(0, evJoin, 0);
    gather1_kernel<<<gather_blocks, 256>>>(b1);

    // ---- layer 2 (relu fused into GEMM input read; pool fused into gather) ----
    gemm2_kernel<<<gemm_blocks, 256>>>(W2);
    gather2_pool_kernel<<<NN / 8, 256>>>(b2, batch, out);
    final_kernel<<<(NG * DD + 255) / 256, 256>>>(out);
}